// round 17
// baseline (speedup 1.0000x reference)
#include <cuda_runtime.h>
#include <cuda_fp16.h>
#include <cstdint>

#define T_TOK 8192
#define DIN   4096
#define DOUT  4096
#define RRANK 64
#define NEXP  16
#define SCALINGF 0.5f
#define NCH_MAIN (DIN / 64)

// ---- scratch (static device globals: allocation-free) ----
__device__ __half g_Xhi[(size_t)T_TOK * DIN];    // 64 MB
__device__ __half g_Xlo[(size_t)T_TOK * DIN];    // 64 MB
__device__ __half g_W  [(size_t)DOUT * DIN];     // 32 MB (base_w fp16)
__device__ __half g_W2 [(size_t)128 * DIN];      // 1 MB  ([A; router; 0])
__device__ float  g_HL [(size_t)T_TOK * 128];    // 4 MB  (h | logits | pad)
__device__ __half g_Hh [(size_t)T_TOK * RRANK];  // 1 MB  (h fp16)
__device__ __half g_Bh [(size_t)NEXP * DOUT * RRANK]; // 8 MB (0.5*B fp16)
__device__ int    g_cnt[NEXP];
__device__ int    g_tok[NEXP * T_TOK];
__device__ float  g_wt [NEXP * T_TOK];

// ---- helpers ----
__device__ __forceinline__ uint32_t smem_u32(const void* p) {
    return (uint32_t)__cvta_generic_to_shared(p);
}
__device__ __forceinline__ void cp_async16(uint32_t dst, const void* src) {
    asm volatile("cp.async.cg.shared.global [%0], [%1], 16;" :: "r"(dst), "l"(src) : "memory");
}
#define CP_COMMIT() asm volatile("cp.async.commit_group;" ::: "memory")
template<int N> __device__ __forceinline__ void cp_wait() {
    asm volatile("cp.async.wait_group %0;" :: "n"(N) : "memory");
}
__device__ __forceinline__ uint32_t sw128(uint32_t off) { return off ^ ((off >> 3) & 0x70); }

__device__ __forceinline__ void ldmx4(uint32_t* r, uint32_t addr) {
    asm volatile("ldmatrix.sync.aligned.m8n8.x4.shared.b16 {%0,%1,%2,%3}, [%4];"
                 : "=r"(r[0]), "=r"(r[1]), "=r"(r[2]), "=r"(r[3]) : "r"(addr));
}
__device__ __forceinline__ void mma16816(float* c, const uint32_t* a, const uint32_t* b) {
    asm volatile(
        "mma.sync.aligned.m16n8k16.row.col.f32.f16.f16.f32 "
        "{%0,%1,%2,%3}, {%4,%5,%6,%7}, {%8,%9}, {%0,%1,%2,%3};"
        : "+f"(c[0]), "+f"(c[1]), "+f"(c[2]), "+f"(c[3])
        : "r"(a[0]), "r"(a[1]), "r"(a[2]), "r"(a[3]), "r"(b[0]), "r"(b[1]));
}

// ---------------------------------------------------------------------------
// Prep kernels
// ---------------------------------------------------------------------------
__global__ void memzero_kernel() {
    if (threadIdx.x < NEXP) g_cnt[threadIdx.x] = 0;
}

__global__ void __launch_bounds__(256) wprep_kernel(const float* __restrict__ bw) {
    size_t i = (size_t)blockIdx.x * 256 + threadIdx.x;
    g_W[i] = __float2half_rn(bw[i]);
}

__global__ void __launch_bounds__(256) bprep_kernel(const float* __restrict__ Bm) {
    size_t i = (size_t)blockIdx.x * 256 + threadIdx.x;
    g_Bh[i] = __float2half_rn(SCALINGF * Bm[i]);
}

__global__ void __launch_bounds__(256) w2prep_kernel(const float* __restrict__ A,
                                                     const float* __restrict__ Rw) {
    int k = blockIdx.x * 256 + threadIdx.x;
    int r = blockIdx.y;
    float v = 0.f;
    if (r < RRANK)             v = A [(size_t)r * DIN + k];
    else if (r < RRANK + NEXP) v = Rw[(size_t)(r - RRANK) * DIN + k];
    g_W2[(size_t)r * DIN + k] = __float2half_rn(v);
}

__global__ void __launch_bounds__(256) xconv_kernel(const float* __restrict__ x) {
    int k = blockIdx.x * 256 + threadIdx.x;
    int t = blockIdx.y;
    float v = x[(size_t)t * DIN + k];
    __half hi = __float2half_rn(v);
    size_t idx = (size_t)t * DIN + k;
    g_Xhi[idx] = hi;
    g_Xlo[idx] = __float2half_rn(v - __half2float(hi));
}

// ---------------------------------------------------------------------------
// Routing GEMM: HL[T,128] = (Xhi+Xlo) @ W2^T  (2-pass hi/lo fp16)
// ---------------------------------------------------------------------------
#define HL_ST_BYTES 32768u
#define HL_SMEM (3 * HL_ST_BYTES + 1024)

__global__ void __launch_bounds__(256, 1) hl_gemm_kernel() {
    extern __shared__ char dyn[];
    uint32_t sbase = (smem_u32(dyn) + 1023u) & ~1023u;
    const int tid = threadIdx.x, wid = tid >> 5, lane = tid & 31;
    const int m0 = blockIdx.y * 64;
    const int wm = (wid & 3) * 16, wn = (wid >> 2) * 64;

    auto load_chunk = [&](int c, int s) {
        uint32_t st = sbase + (uint32_t)s * HL_ST_BYTES;
        size_t gk = (size_t)c * 64;
        #pragma unroll
        for (int u = 0; u < 2; u++) {
            int v = u * 256 + tid; int row = v >> 3, c16 = v & 7;
            uint32_t so = sw128((uint32_t)(row * 128 + c16 * 16));
            cp_async16(st + so,         g_Xhi + (size_t)(m0 + row) * DIN + gk + c16 * 8);
            cp_async16(st + 8192u + so, g_Xlo + (size_t)(m0 + row) * DIN + gk + c16 * 8);
        }
        #pragma unroll
        for (int u = 0; u < 4; u++) {
            int v = u * 256 + tid; int row = v >> 3, c16 = v & 7;
            uint32_t so = sw128((uint32_t)(row * 128 + c16 * 16));
            cp_async16(st + 16384u + so, g_W2 + (size_t)row * DIN + gk + c16 * 8);
        }
    };

    float acc[8][4];
    #pragma unroll
    for (int j = 0; j < 8; j++)
        #pragma unroll
        for (int q = 0; q < 4; q++) acc[j][q] = 0.f;

    load_chunk(0, 0); CP_COMMIT();
    load_chunk(1, 1); CP_COMMIT();

    for (int c = 0; c < NCH_MAIN; c++) {
        cp_wait<1>();
        __syncthreads();
        if (c + 2 < NCH_MAIN) { load_chunk(c + 2, (c + 2) % 3); CP_COMMIT(); }

        uint32_t st = sbase + (uint32_t)(c % 3) * HL_ST_BYTES;
        #pragma unroll
        for (int kk = 0; kk < 64; kk += 16) {
            uint32_t ah[4], al[4], bb[16];
            {
                int row = wm + (lane & 7) + ((lane >> 3) & 1) * 8;
                int kb  = kk + (lane >> 4) * 8;
                uint32_t so = sw128((uint32_t)(row * 128 + kb * 2));
                ldmx4(ah, st + so);
                ldmx4(al, st + 8192u + so);
            }
            #pragma unroll
            for (int nt = 0; nt < 4; nt++) {
                int nrow = wn + nt * 16 + (lane & 7) + (lane >> 4) * 8;
                int kb   = kk + ((lane >> 3) & 1) * 8;
                ldmx4(bb + nt * 4, st + 16384u + sw128((uint32_t)(nrow * 128 + kb * 2)));
            }
            #pragma unroll
            for (int nj = 0; nj < 8; nj++) {
                mma16816(acc[nj], ah, bb + nj * 2);
                mma16816(acc[nj], al, bb + nj * 2);
            }
        }
    }

    int r0 = m0 + wm + (lane >> 2);
    #pragma unroll
    for (int nj = 0; nj < 8; nj++) {
        int col = wn + nj * 8 + (lane & 3) * 2;
        float* p = g_HL + (size_t)r0 * 128 + col;
        p[0] = acc[nj][0]; p[1] = acc[nj][1];
        p[128 * 8] = acc[nj][2]; p[128 * 8 + 1] = acc[nj][3];
    }
}

// ---------------------------------------------------------------------------
// Routing post: softmax/top2, store h fp16, push (token, weight) buckets
// ---------------------------------------------------------------------------
__global__ void __launch_bounds__(64) hlpost_kernel() {
    int t = blockIdx.x, tid = threadIdx.x;
    g_Hh[(size_t)t * RRANK + tid] = __float2half_rn(g_HL[(size_t)t * 128 + tid]);
    if (tid == 0) {
        const float* lg = g_HL + (size_t)t * 128 + RRANK;
        float mx = -1e30f;
        for (int e = 0; e < NEXP; e++) mx = fmaxf(mx, lg[e]);
        float p[NEXP], se = 0.f;
        for (int e = 0; e < NEXP; e++) { p[e] = expf(lg[e] - mx); se += p[e]; }
        for (int e = 0; e < NEXP; e++) p[e] /= se;
        int i1 = 0;
        for (int e = 1; e < NEXP; e++) if (p[e] > p[i1]) i1 = e;
        int i2 = (i1 == 0) ? 1 : 0;
        for (int e = 0; e < NEXP; e++) if (e != i1 && p[e] > p[i2]) i2 = e;
        float swt = p[i1] + p[i2] + 1e-6f;
        int q1 = atomicAdd(&g_cnt[i1], 1);
        g_tok[i1 * T_TOK + q1] = t;  g_wt[i1 * T_TOK + q1] = p[i1] / swt;
        int q2 = atomicAdd(&g_cnt[i2], 1);
        g_tok[i2 * T_TOK + q2] = t;  g_wt[i2 * T_TOK + q2] = p[i2] / swt;
    }
}

// ---------------------------------------------------------------------------
// Main GEMM: out[T,DOUT] = Xhi @ W^T + bias  (fp16 mma.sync, f32 acc, K=4096)
// ---------------------------------------------------------------------------
#define BM 128
#define BN 256
#define STAGE_BYTES 49152u
#define GEMM_SMEM (3 * STAGE_BYTES + 1024)

__global__ void __launch_bounds__(256, 1) gemm_kernel(const float* __restrict__ bias,
                                                      float* __restrict__ out) {
    extern __shared__ char dyn[];
    uint32_t sbase = (smem_u32(dyn) + 1023u) & ~1023u;
    const int tid = threadIdx.x, wid = tid >> 5, lane = tid & 31;
    const int m0 = blockIdx.y * BM, n0 = blockIdx.x * BN;
    const int wm = (wid & 1) * 64, wn = (wid >> 1) * 64;

    auto load_chunk = [&](int c, int s) {
        uint32_t st = sbase + (uint32_t)s * STAGE_BYTES;
        size_t gk = (size_t)c * 64;
        #pragma unroll
        for (int u = 0; u < 4; u++) {
            int v = u * 256 + tid; int row = v >> 3, c16 = v & 7;
            uint32_t so = sw128((uint32_t)(row * 128 + c16 * 16));
            cp_async16(st + so, g_Xhi + (size_t)(m0 + row) * DIN + gk + c16 * 8);
        }
        #pragma unroll
        for (int u = 0; u < 8; u++) {
            int v = u * 256 + tid; int row = v >> 3, c16 = v & 7;
            uint32_t so = sw128((uint32_t)(row * 128 + c16 * 16));
            cp_async16(st + 16384u + so, g_W + (size_t)(n0 + row) * DIN + gk + c16 * 8);
        }
    };

    float acc[4][8][4];
    #pragma unroll
    for (int i = 0; i < 4; i++)
        #pragma unroll
        for (int j = 0; j < 8; j++)
            #pragma unroll
            for (int q = 0; q < 4; q++) acc[i][j][q] = 0.f;

    load_chunk(0, 0); CP_COMMIT();
    load_chunk(1, 1); CP_COMMIT();

    for (int c = 0; c < NCH_MAIN; c++) {
        cp_wait<1>();
        __syncthreads();
        if (c + 2 < NCH_MAIN) { load_chunk(c + 2, (c + 2) % 3); CP_COMMIT(); }

        uint32_t st = sbase + (uint32_t)(c % 3) * STAGE_BYTES;
        #pragma unroll
        for (int kk = 0; kk < 64; kk += 16) {
            uint32_t ah[16], bb[16];
            #pragma unroll
            for (int mt = 0; mt < 4; mt++) {
                int row = wm + mt * 16 + (lane & 7) + ((lane >> 3) & 1) * 8;
                int kb  = kk + (lane >> 4) * 8;
                ldmx4(ah + mt * 4, st + sw128((uint32_t)(row * 128 + kb * 2)));
            }
            #pragma unroll
            for (int nt = 0; nt < 4; nt++) {
                int nrow = wn + nt * 16 + (lane & 7) + (lane >> 4) * 8;
                int kb   = kk + ((lane >> 3) & 1) * 8;
                ldmx4(bb + nt * 4, st + 16384u + sw128((uint32_t)(nrow * 128 + kb * 2)));
            }
            #pragma unroll
            for (int mt = 0; mt < 4; mt++)
                #pragma unroll
                for (int nj = 0; nj < 8; nj++)
                    mma16816(acc[mt][nj], ah + mt * 4, bb + nj * 2);
        }
    }

    #pragma unroll
    for (int mt = 0; mt < 4; mt++) {
        int r0 = m0 + wm + mt * 16 + (lane >> 2);
        #pragma unroll
        for (int nj = 0; nj < 8; nj++) {
            int col = n0 + wn + nj * 8 + (lane & 3) * 2;
            float b0 = __ldg(bias + col), b1 = __ldg(bias + col + 1);
            float* p = out + (size_t)r0 * DOUT + col;
            p[0] = acc[mt][nj][0] + b0;
            p[1] = acc[mt][nj][1] + b1;
            float* q = p + (size_t)8 * DOUT;
            q[0] = acc[mt][nj][2] + b0;
            q[1] = acc[mt][nj][3] + b1;
        }
    }
}

// ---------------------------------------------------------------------------
// Sparse MoE delta: per (expert, n-tile 256), loop 64-token m-tiles of bucket;
// out[t, n] += w * (h[t] @ (0.5*B_e)^T)   via fp16 mma + atomicAdd.
// ---------------------------------------------------------------------------
__global__ void __launch_bounds__(256) delta_kernel(float* __restrict__ out) {
    __shared__ __align__(1024) char sB[32768];   // B_e: 256 n-rows x 128B
    __shared__ __align__(1024) char sH[8192];    // h:    64 t-rows x 128B
    __shared__ int   stok[64];
    __shared__ float swt[64];

    const int e = blockIdx.y, n0 = blockIdx.x * 256;
    const int cnt = g_cnt[e];
    if (cnt == 0) return;
    const int tid = threadIdx.x, wid = tid >> 5, lane = tid & 31;
    const int wm = (wid & 1) * 32, wn = (wid >> 1) * 64;
    uint32_t bB = smem_u32(sB), bH = smem_u32(sH);

    // stage B_e tile once
    #pragma unroll
    for (int u = 0; u < 8; u++) {
        int v = u * 256 + tid; int row = v >> 3, c16 = v & 7;
        cp_async16(bB + sw128((uint32_t)(row * 128 + c16 * 16)),
                   g_Bh + ((size_t)e * DOUT + n0 + row) * RRANK + c16 * 8);
    }
    CP_COMMIT();

    for (int m0 = 0; m0 < cnt; m0 += 64) {
        int rem = cnt - m0;
        if (tid < 64) {
            if (tid < rem) { stok[tid] = g_tok[e * T_TOK + m0 + tid]; swt[tid] = g_wt[e * T_TOK + m0 + tid]; }
            else           { stok[tid] = 0; swt[tid] = 0.f; }
        }
        #pragma unroll
        for (int u = 0; u < 2; u++) {
            int v = u * 256 + tid; int row = v >> 3, c16 = v & 7;
            int tk = g_tok[e * T_TOK + m0 + ((row < rem) ? row : 0)];
            cp_async16(bH + sw128((uint32_t)(row * 128 + c16 * 16)),
                       g_Hh + (size_t)tk * RRANK + c16 * 8);
        }
        CP_COMMIT();
        cp_wait<0>();
        __syncthreads();

        float acc[2][8][4];
        #pragma unroll
        for (int i = 0; i < 2; i++)
            #pragma unroll
            for (int j = 0; j < 8; j++)
                #pragma unroll
                for (int q = 0; q < 4; q++) acc[i][j][q] = 0.f;

        #pragma unroll
        for (int kk = 0; kk < 64; kk += 16) {
            uint32_t ah[8], bb[16];
            #pragma unroll
            for (int mt = 0; mt < 2; mt++) {
                int row = wm + mt * 16 + (lane & 7) + ((lane >> 3) & 1) * 8;
                int kb  = kk + (lane >> 4) * 8;
                ldmx4(ah + mt * 4, bH + sw128((uint32_t)(row * 128 + kb * 2)));
            }
            #pragma unroll
            for (int nt = 0; nt < 4; nt++) {
                int nrow = wn + nt * 16 + (lane & 7) + (lane >> 4) * 8;
                int kb   = kk + ((lane >> 3) & 1) * 8;
                ldmx4(bb + nt * 4, bB + sw128((uint32_t)(nrow * 128 + kb * 2)));
            }
            #pragma unroll
            for (int mt = 0; mt < 2; mt++)
                #pragma unroll
                for (int nj = 0; nj < 8; nj++)
                    mma16816(acc[mt][nj], ah + mt * 4, bb + nj * 2);
        }

        #pragma unroll
        for (int mt = 0; mt < 2; mt++) {
            int r0 = wm + mt * 16 + (lane >> 2), r1 = r0 + 8;
            int   t0 = stok[r0], t1 = stok[r1];
            float w0 = swt[r0],  w1 = swt[r1];
            #pragma unroll
            for (int nj = 0; nj < 8; nj++) {
                int col = n0 + wn + nj * 8 + (lane & 3) * 2;
                if (w0 != 0.f) {
                    atomicAdd(&out[(size_t)t0 * DOUT + col],     w0 * acc[mt][nj][0]);
                    atomicAdd(&out[(size_t)t0 * DOUT + col + 1], w0 * acc[mt][nj][1]);
                }
                if (w1 != 0.f) {
                    atomicAdd(&out[(size_t)t1 * DOUT + col],     w1 * acc[mt][nj][2]);
                    atomicAdd(&out[(size_t)t1 * DOUT + col + 1], w1 * acc[mt][nj][3]);
                }
            }
        }
        __syncthreads();   // protect sH/stok before next m-tile overwrite
    }
}

// ---------------------------------------------------------------------------
// kernel_launch
// ---------------------------------------------------------------------------
extern "C" void kernel_launch(void* const* d_in, const int* in_sizes, int n_in,
                              void* d_out, int out_size) {
    const float* x      = (const float*)d_in[0];
    const float* base_w = (const float*)d_in[1];
    const float* base_b = (const float*)d_in[2];
    const float* A      = (const float*)d_in[3];
    const float* Bm     = (const float*)d_in[4];
    const float* router = (const float*)d_in[5];
    float* out = (float*)d_out;

    cudaFuncSetAttribute(gemm_kernel, cudaFuncAttributeMaxDynamicSharedMemorySize, GEMM_SMEM);
    cudaFuncSetAttribute(hl_gemm_kernel, cudaFuncAttributeMaxDynamicSharedMemorySize, HL_SMEM);

    memzero_kernel<<<1, 32>>>();
    wprep_kernel<<<(unsigned)(((size_t)DOUT * DIN) / 256), 256>>>(base_w);
    bprep_kernel<<<(unsigned)(((size_t)NEXP * DOUT * RRANK) / 256), 256>>>(Bm);
    w2prep_kernel<<<dim3(DIN / 256, 128), 256>>>(A, router);
    xconv_kernel<<<dim3(DIN / 256, T_TOK), 256>>>(x);
    hl_gemm_kernel<<<dim3(1, T_TOK / 64), 256, HL_SMEM>>>();
    hlpost_kernel<<<T_TOK, 64>>>();
    gemm_kernel<<<dim3(DOUT / BN, T_TOK / BM), 256, GEMM_SMEM>>>(base_b, out);
    delta_kernel<<<dim3(DOUT / 256, NEXP), 256>>>(out);
}